// round 4
// baseline (speedup 1.0000x reference)
#include <cuda_runtime.h>
#include <math.h>

#define Hc 128
#define Wc 128
#define HWc 16384

typedef unsigned long long u64p;

// packed f32x2 helpers (sm_100+ PTX)
__device__ __forceinline__ u64p pk(float lo, float hi) {
  u64p r; asm("mov.b64 %0, {%1,%2};" : "=l"(r) : "f"(lo), "f"(hi)); return r;
}
__device__ __forceinline__ void fma2(u64p& a, u64p x, u64p y) {
  asm("fma.rn.f32x2 %0, %1, %2, %0;" : "+l"(a) : "l"(x), "l"(y));
}
// a = a*x + c
__device__ __forceinline__ void fma2b(u64p& a, u64p x, u64p c) {
  asm("fma.rn.f32x2 %0, %0, %1, %2;" : "+l"(a) : "l"(x), "l"(c));
}
__device__ __forceinline__ float2 up(u64p v) {
  float2 f; asm("mov.b64 {%0,%1}, %2;" : "=f"(f.x), "=f"(f.y) : "l"(v)); return f;
}

// Scratch (static device globals; runtime allocation forbidden)
__device__ float g_x1[2*64*HWc];
__device__ float g_f [2*32*HWc];
__device__ float g_zp[2*2*HWc];
__device__ float g_x2[2*64*HWc];
__device__ float g_h [2*32*HWc];

// ---------------------------------------------------------------------------
// K1: one row (128 px). conv1 (128->64)+PReLU -> x1 ; reduce (64->32)+ReLU -> f;
// ZPool -> zp. f32x2-packed register tiles.
// ---------------------------------------------------------------------------
__global__ __launch_bounds__(256, 2) void k_front(
    const float* __restrict__ x,  const float* __restrict__ w1,
    const float* __restrict__ b1, const float* __restrict__ a1p,
    const float* __restrict__ wr, const float* __restrict__ br)
{
  extern __shared__ float sm[];
  float* xs  = sm;              // 32*132
  float* w1t = xs + 4224;       // 8192  [c][oc]
  float* x1s = w1t + 8192;      // 64*132
  float* wrt = x1s + 8448;      // 2048  [c][oc]
  float* fs  = wrt + 2048;      // 32*132
  const int t = threadIdx.x;
  const int h = blockIdx.x & 127;
  const int b = blockIdx.x >> 7;
  const float a1 = *a1p;

  for (int i = t; i < 8192; i += 256) { int c = i >> 6, oc = i & 63; w1t[i] = w1[oc*128 + c]; }
  for (int i = t; i < 2048; i += 256) { int c = i >> 5, oc = i & 31; wrt[i] = wr[oc*64 + c]; }

  const int oc0 = (t >> 4) * 4;
  const int px0 = (t & 15) * 8;
  u64p acc[4][4];
  #pragma unroll
  for (int o = 0; o < 4; o++) {
    float bv = b1[oc0 + o];
    u64p bp = pk(bv, bv);
    #pragma unroll
    for (int p = 0; p < 4; p++) acc[o][p] = bp;
  }

  const float* xb = x + (b*128)*HWc + h*Wc;
  for (int cc = 0; cc < 4; cc++) {
    __syncthreads();
    for (int i = t; i < 4096; i += 256) {
      int ci = i >> 7, p = i & 127;
      xs[ci*132 + p] = xb[(cc*32 + ci)*HWc + p];
    }
    __syncthreads();
    #pragma unroll 4
    for (int ci = 0; ci < 32; ci++) {
      const int c = cc*32 + ci;
      float4 wv  = *(const float4*)&w1t[c*64 + oc0];
      float4 xa  = *(const float4*)&xs[ci*132 + px0];
      float4 xb4 = *(const float4*)&xs[ci*132 + px0 + 4];
      u64p xp[4] = {pk(xa.x,xa.y), pk(xa.z,xa.w), pk(xb4.x,xb4.y), pk(xb4.z,xb4.w)};
      u64p wd[4] = {pk(wv.x,wv.x), pk(wv.y,wv.y), pk(wv.z,wv.z), pk(wv.w,wv.w)};
      #pragma unroll
      for (int o = 0; o < 4; o++)
        #pragma unroll
        for (int p = 0; p < 4; p++)
          fma2(acc[o][p], wd[o], xp[p]);
    }
  }

  float* gx1b = g_x1 + (b*64)*HWc + h*Wc;
  #pragma unroll
  for (int o = 0; o < 4; o++) {
    float v4[8];
    #pragma unroll
    for (int p = 0; p < 4; p++) {
      float2 v = up(acc[o][p]);
      v4[2*p]   = (v.x >= 0.f) ? v.x : a1*v.x;
      v4[2*p+1] = (v.y >= 0.f) ? v.y : a1*v.y;
    }
    *(float4*)&x1s[(oc0+o)*132 + px0]     = make_float4(v4[0],v4[1],v4[2],v4[3]);
    *(float4*)&x1s[(oc0+o)*132 + px0 + 4] = make_float4(v4[4],v4[5],v4[6],v4[7]);
    *(float4*)&gx1b[(oc0+o)*HWc + px0]     = make_float4(v4[0],v4[1],v4[2],v4[3]);
    *(float4*)&gx1b[(oc0+o)*HWc + px0 + 4] = make_float4(v4[4],v4[5],v4[6],v4[7]);
  }
  __syncthreads();

  // reduce: 32 oc x 128 px
  const int ocr = (t >> 5) * 4;
  const int pxr = (t & 31) * 4;
  u64p racc[4][2];
  #pragma unroll
  for (int o = 0; o < 4; o++) {
    float bv = br[ocr + o];
    u64p bp = pk(bv, bv);
    racc[o][0] = bp; racc[o][1] = bp;
  }
  #pragma unroll 4
  for (int c = 0; c < 64; c++) {
    float4 wv = *(const float4*)&wrt[c*32 + ocr];
    float4 xv = *(const float4*)&x1s[c*132 + pxr];
    u64p xp[2] = {pk(xv.x,xv.y), pk(xv.z,xv.w)};
    u64p wd[4] = {pk(wv.x,wv.x), pk(wv.y,wv.y), pk(wv.z,wv.z), pk(wv.w,wv.w)};
    #pragma unroll
    for (int o = 0; o < 4; o++) {
      fma2(racc[o][0], wd[o], xp[0]);
      fma2(racc[o][1], wd[o], xp[1]);
    }
  }
  float* gfb = g_f + (b*32)*HWc + h*Wc;
  #pragma unroll
  for (int o = 0; o < 4; o++) {
    float2 v0 = up(racc[o][0]), v1 = up(racc[o][1]);
    float4 v = make_float4(fmaxf(v0.x,0.f), fmaxf(v0.y,0.f), fmaxf(v1.x,0.f), fmaxf(v1.y,0.f));
    *(float4*)&fs[(ocr+o)*132 + pxr] = v;
    *(float4*)&gfb[(ocr+o)*HWc + pxr] = v;
  }
  __syncthreads();

  if (t < 128) {
    float mx = -1e30f, sum = 0.f;
    #pragma unroll
    for (int c = 0; c < 32; c++) {
      float v = fs[c*132 + t];
      mx = fmaxf(mx, v);
      sum += v;
    }
    g_zp[(b*2)*HWc + h*Wc + t]   = mx;
    g_zp[(b*2+1)*HWc + h*Wc + t] = sum * (1.f/32.f);
  }
}

// ---------------------------------------------------------------------------
// K2: involution. Tile 32x2 px. Span kernels with f32x2-packed FMA.
// ---------------------------------------------------------------------------
__global__ __launch_bounds__(256, 2) void k_inv(
    const float* __restrict__ ws, const float* __restrict__ bs,
    const float* __restrict__ a2p)
{
  extern __shared__ float sm[];
  float* x1h = sm;                // 64ch * 8row * 38col = 19456
  float* wss = x1h + 19456;       // 6272
  float* bss = wss + 6272;        // 196
  float* fts = bss + 196;         // 64*33
  const int t = threadIdx.x;
  const int w0 = blockIdx.x << 5;
  const int h0 = blockIdx.y << 1;
  const int b  = blockIdx.z;
  const float a2 = *a2p;

  const float* gx1b = g_x1 + (b*64)*HWc;
  for (int i = t; i < 19456; i += 256) {
    int ch = i / 304, r = i - ch*304;
    int yy = r / 38, xx = r - yy*38;
    int gh = h0 - 3 + yy, gw = w0 - 3 + xx;
    float v = 0.f;
    if ((unsigned)gh < 128u && (unsigned)gw < 128u)
      v = gx1b[ch*HWc + gh*Wc + gw];
    x1h[i] = v;
  }
  for (int i = t; i < 6272; i += 256) wss[i] = ws[i];
  if (t < 196) bss[t] = bs[t];
  const float* gfb = g_f + (b*32)*HWc;
  for (int i = t; i < 2048; i += 256) {
    int c = i >> 6, p = i & 63;
    fts[p*33 + c] = gfb[c*HWc + (h0 + (p>>5))*Wc + w0 + (p&31)];
  }
  __syncthreads();

  const int p = t & 63, j = t >> 6;
  const int py = p >> 5, px = p & 31;

  u64p fp[16];
  #pragma unroll
  for (int c2 = 0; c2 < 16; c2++)
    fp[c2] = pk(fts[p*33 + 2*c2], fts[p*33 + 2*c2 + 1]);

  float acc[16];
  #pragma unroll
  for (int ch = 0; ch < 16; ch++) acc[ch] = 0.f;

  const float* wb = wss + j*49*32;
  const float* bb = bss + j*49;
  const float* xb = x1h + (j*16)*304 + py*38 + px;

  #pragma unroll 1
  for (int dy = 0; dy < 7; dy++) {
    #pragma unroll 1
    for (int dx = 0; dx < 7; dx++) {
      const int tt = dy*7 + dx;
      const float* wr2 = wb + tt*32;
      u64p k0 = 0ull, k1 = 0ull;
      #pragma unroll
      for (int c4 = 0; c4 < 8; c4++) {
        float4 wv = *(const float4*)&wr2[c4*4];
        fma2(k0, pk(wv.x, wv.y), fp[2*c4]);
        fma2(k1, pk(wv.z, wv.w), fp[2*c4 + 1]);
      }
      float2 ka = up(k0), kb = up(k1);
      const float kwt = bb[tt] + ((ka.x + ka.y) + (kb.x + kb.y));
      const float* src = xb + dy*38 + dx;
      #pragma unroll
      for (int ch = 0; ch < 16; ch++)
        acc[ch] += kwt * src[ch*304];
    }
  }

  float* gx2b = g_x2 + (b*64 + j*16)*HWc + (h0 + py)*Wc + (w0 + px);
  #pragma unroll
  for (int ch = 0; ch < 16; ch++) {
    float v = acc[ch];
    gx2b[ch*HWc] = (v >= 0.f) ? v : a2*v;
  }
}

// ---------------------------------------------------------------------------
// K3: psec 3x3 conv (32->32) + PReLU. Retiled to 16x8 (256 blocks, fills chip).
// 256 thr: 4 oc-groups(8oc, packed pairs) x 64 px-threads (2 px each).
// ---------------------------------------------------------------------------
__global__ __launch_bounds__(256) void k_psec1(
    const float* __restrict__ wp1, const float* __restrict__ bp1,
    const float* __restrict__ app)
{
  extern __shared__ float sm[];
  float* fh  = sm;            // 32*180 = 5760 (10 rows x 18 cols per ch)
  float* wpt = fh + 5760;     // 9216 [ci*9+tap][oc]
  const int t = threadIdx.x;
  const int w0 = blockIdx.x << 4;   // 8 x-tiles of 16
  const int h0 = blockIdx.y << 3;   // 16 y-tiles of 8
  const int b  = blockIdx.z;
  const float ap = *app;

  const float* gfb = g_f + (b*32)*HWc;
  for (int i = t; i < 5760; i += 256) {
    int c = i / 180, r = i - c*180;
    int yy = r / 18, xx = r - yy*18;
    int gh = h0 - 1 + yy, gw = w0 - 1 + xx;
    float v = 0.f;
    if ((unsigned)gh < 128u && (unsigned)gw < 128u)
      v = gfb[c*HWc + gh*Wc + gw];
    fh[i] = v;
  }
  for (int i = t; i < 9216; i += 256) {
    int tc = i >> 5, o = i & 31;
    wpt[i] = wp1[o*288 + tc];
  }
  __syncthreads();

  const int oc0 = (t >> 6) * 8;          // 4 groups x 8 oc
  const int pg  = t & 63;
  const int py  = pg >> 3;               // 0..7
  const int px0 = (pg & 7) * 2;          // 0..14

  u64p acc[4][2];   // oc pairs x 2 px
  #pragma unroll
  for (int o2 = 0; o2 < 4; o2++) {
    u64p bp = pk(bp1[oc0 + 2*o2], bp1[oc0 + 2*o2 + 1]);
    acc[o2][0] = bp; acc[o2][1] = bp;
  }

  #pragma unroll 1
  for (int ci = 0; ci < 32; ci++) {
    #pragma unroll
    for (int tap = 0; tap < 9; tap++) {
      const int di = tap / 3, dj = tap - di*3;
      float4 wa4 = *(const float4*)&wpt[(ci*9 + tap)*32 + oc0];
      float4 wb4 = *(const float4*)&wpt[(ci*9 + tap)*32 + oc0 + 4];
      u64p wp2_[4] = {pk(wa4.x,wa4.y), pk(wa4.z,wa4.w), pk(wb4.x,wb4.y), pk(wb4.z,wb4.w)};
      const float* fr = &fh[ci*180 + (py + di)*18 + px0 + dj];
      u64p xd[2] = {pk(fr[0], fr[0]), pk(fr[1], fr[1])};
      #pragma unroll
      for (int o2 = 0; o2 < 4; o2++) {
        fma2(acc[o2][0], wp2_[o2], xd[0]);
        fma2(acc[o2][1], wp2_[o2], xd[1]);
      }
    }
  }

  float* ghb = g_h + (b*32)*HWc + (h0 + py)*Wc + (w0 + px0);
  #pragma unroll
  for (int o2 = 0; o2 < 4; o2++) {
    float2 v0 = up(acc[o2][0]);   // oc pair at px0
    float2 v1 = up(acc[o2][1]);   // oc pair at px0+1
    float a0 = (v0.x >= 0.f) ? v0.x : ap*v0.x;
    float b0 = (v0.y >= 0.f) ? v0.y : ap*v0.y;
    float a1v = (v1.x >= 0.f) ? v1.x : ap*v1.x;
    float b1v = (v1.y >= 0.f) ? v1.y : ap*v1.y;
    *(float2*)&ghb[(oc0 + 2*o2)*HWc]     = make_float2(a0, a1v);
    *(float2*)&ghb[(oc0 + 2*o2 + 1)*HWc] = make_float2(b0, b1v);
  }
}

// ---------------------------------------------------------------------------
// K4: one row (128 px), 128 oc. Thread = 8oc x 8px, f32x2-packed over px.
// ---------------------------------------------------------------------------
__global__ __launch_bounds__(256, 2) void k_final(
    const float* __restrict__ w2,  const float* __restrict__ b2,
    const float* __restrict__ wa,  const float* __restrict__ ba,
    const float* __restrict__ wp2, const float* __restrict__ bp2,
    float* __restrict__ out)
{
  extern __shared__ float sm[];
  float* x2t   = sm;             // 64*132
  float* ht    = x2t + 8448;     // 32*132
  float* w2t   = ht + 4224;      // 8192 [c][oc]
  float* wpt   = w2t + 8192;     // 4096 [c][oc]
  float* zph   = wpt + 4096;     // 2*7*136
  float* was   = zph + 1904;     // 98
  float* attns = was + 98;       // 128
  const int t = threadIdx.x;
  const int h = blockIdx.x & 127;
  const int b = blockIdx.x >> 7;

  const float* gx2b = g_x2 + (b*64)*HWc + h*Wc;
  for (int i = t; i < 8192; i += 256) { int c = i >> 7, p = i & 127; x2t[c*132 + p] = gx2b[c*HWc + p]; }
  const float* ghb = g_h + (b*32)*HWc + h*Wc;
  for (int i = t; i < 4096; i += 256) { int c = i >> 7, p = i & 127; ht[c*132 + p] = ghb[c*HWc + p]; }
  for (int i = t; i < 8192; i += 256) { int c = i >> 7, oc = i & 127; w2t[i] = w2[oc*64 + c]; }
  for (int i = t; i < 4096; i += 256) { int c = i >> 7, oc = i & 127; wpt[i] = wp2[oc*32 + c]; }
  const float* gzb = g_zp + (b*2)*HWc;
  for (int i = t; i < 1904; i += 256) {
    int c = i / 952, r = i - c*952;
    int yy = r / 136, xx = r - yy*136;
    int gh = h - 3 + yy, gw = xx - 3;
    float v = 0.f;
    if ((unsigned)gh < 128u && (unsigned)gw < 128u)
      v = gzb[c*HWc + gh*Wc + gw];
    zph[i] = v;
  }
  if (t < 98) was[t] = wa[t];
  __syncthreads();

  if (t < 128) {
    float aacc = *ba;
    #pragma unroll
    for (int dy = 0; dy < 7; dy++)
      #pragma unroll
      for (int dx = 0; dx < 7; dx++) {
        const int o1 = dy*136 + t + dx;
        aacc += was[dy*7+dx]*zph[o1] + was[49 + dy*7+dx]*zph[952 + o1];
      }
    attns[t] = 1.f / (1.f + expf(-aacc));
  }
  __syncthreads();

  const int oc0 = (t >> 4) * 8;
  const int px0 = (t & 15) * 8;
  u64p acc[8][4];
  #pragma unroll
  for (int o = 0; o < 8; o++) {
    float bv = b2[oc0 + o];
    u64p bp = pk(bv, bv);
    #pragma unroll
    for (int p = 0; p < 4; p++) acc[o][p] = bp;
  }

  #pragma unroll 2
  for (int c = 0; c < 64; c++) {
    float4 wva = *(const float4*)&w2t[c*128 + oc0];
    float4 wvb = *(const float4*)&w2t[c*128 + oc0 + 4];
    float4 xa  = *(const float4*)&x2t[c*132 + px0];
    float4 xb4 = *(const float4*)&x2t[c*132 + px0 + 4];
    u64p xp[4] = {pk(xa.x,xa.y), pk(xa.z,xa.w), pk(xb4.x,xb4.y), pk(xb4.z,xb4.w)};
    u64p wd[8] = {pk(wva.x,wva.x), pk(wva.y,wva.y), pk(wva.z,wva.z), pk(wva.w,wva.w),
                  pk(wvb.x,wvb.x), pk(wvb.y,wvb.y), pk(wvb.z,wvb.z), pk(wvb.w,wvb.w)};
    #pragma unroll
    for (int o = 0; o < 8; o++)
      #pragma unroll
      for (int p = 0; p < 4; p++)
        fma2(acc[o][p], wd[o], xp[p]);
  }

  u64p attp[4];
  #pragma unroll
  for (int p = 0; p < 4; p++) attp[p] = pk(attns[px0 + 2*p], attns[px0 + 2*p + 1]);
  #pragma unroll
  for (int o = 0; o < 8; o++) {
    float bpv = bp2[oc0 + o];
    u64p bpp = pk(bpv, bpv);
    #pragma unroll
    for (int p = 0; p < 4; p++) fma2b(acc[o][p], attp[p], bpp);
  }

  #pragma unroll 2
  for (int c = 0; c < 32; c++) {
    float4 wva = *(const float4*)&wpt[c*128 + oc0];
    float4 wvb = *(const float4*)&wpt[c*128 + oc0 + 4];
    float4 ha  = *(const float4*)&ht[c*132 + px0];
    float4 hb4 = *(const float4*)&ht[c*132 + px0 + 4];
    u64p hp[4] = {pk(ha.x,ha.y), pk(ha.z,ha.w), pk(hb4.x,hb4.y), pk(hb4.z,hb4.w)};
    u64p wd[8] = {pk(wva.x,wva.x), pk(wva.y,wva.y), pk(wva.z,wva.z), pk(wva.w,wva.w),
                  pk(wvb.x,wvb.x), pk(wvb.y,wvb.y), pk(wvb.z,wvb.z), pk(wvb.w,wvb.w)};
    #pragma unroll
    for (int o = 0; o < 8; o++)
      #pragma unroll
      for (int p = 0; p < 4; p++)
        fma2(acc[o][p], wd[o], hp[p]);
  }

  float* ob = out + (b*128 + oc0)*HWc + h*Wc + px0;
  #pragma unroll
  for (int o = 0; o < 8; o++) {
    float2 v0 = up(acc[o][0]), v1 = up(acc[o][1]), v2 = up(acc[o][2]), v3 = up(acc[o][3]);
    *(float4*)&ob[o*HWc]     = make_float4(v0.x, v0.y, v1.x, v1.y);
    *(float4*)&ob[o*HWc + 4] = make_float4(v2.x, v2.y, v3.x, v3.y);
  }
}

// ---------------------------------------------------------------------------
extern "C" void kernel_launch(void* const* d_in, const int* in_sizes, int n_in,
                              void* d_out, int out_size)
{
  const float* x   = (const float*)d_in[0];
  const float* w1  = (const float*)d_in[1];
  const float* b1  = (const float*)d_in[2];
  const float* a1  = (const float*)d_in[3];
  const float* wr  = (const float*)d_in[4];
  const float* br  = (const float*)d_in[5];
  const float* ws  = (const float*)d_in[6];
  const float* bs  = (const float*)d_in[7];
  const float* a2  = (const float*)d_in[8];
  const float* w2  = (const float*)d_in[9];
  const float* b2  = (const float*)d_in[10];
  const float* wa  = (const float*)d_in[11];
  const float* ba  = (const float*)d_in[12];
  const float* wp1 = (const float*)d_in[13];
  const float* bp1 = (const float*)d_in[14];
  const float* ap  = (const float*)d_in[15];
  const float* wp2 = (const float*)d_in[16];
  const float* bp2 = (const float*)d_in[17];
  float* out = (float*)d_out;

  const int s1 = 27136 * 4;   // k_front
  const int s2 = 28036 * 4;   // k_inv
  const int s3 = 14976 * 4;   // k_psec1
  const int s4 = 27090 * 4;   // k_final

  cudaFuncSetAttribute(k_front, cudaFuncAttributeMaxDynamicSharedMemorySize, s1);
  cudaFuncSetAttribute(k_inv,   cudaFuncAttributeMaxDynamicSharedMemorySize, s2);
  cudaFuncSetAttribute(k_psec1, cudaFuncAttributeMaxDynamicSharedMemorySize, s3);
  cudaFuncSetAttribute(k_final, cudaFuncAttributeMaxDynamicSharedMemorySize, s4);

  k_front<<<256, 256, s1>>>(x, w1, b1, a1, wr, br);
  k_inv  <<<dim3(4, 64, 2), 256, s2>>>(ws, bs, a2);
  k_psec1<<<dim3(8, 16, 2), 256, s3>>>(wp1, bp1, ap);
  k_final<<<256, 256, s4>>>(w2, b2, wa, ba, wp2, bp2, out);
}